// round 1
// baseline (speedup 1.0000x reference)
#include <cuda_runtime.h>
#include <math.h>

#define NN 10000      // nodes
#define TT 12         // seq len
#define FIN 16        // in channels
#define HH 64         // hidden
#define K3 192        // 3*H
#define NE 160000     // edges
#define NT (NN*TT)    // 120000 rows

// ---------------- scratch (device globals; no allocation allowed) ----------
__device__ float g_deg[NN];
__device__ float g_dis[NN];
__device__ float g_agg[NN * TT * FIN];     // (n,t,f)   7.68 MB
__device__ float g_gcn[NN * TT * HH];      // (n,t,h)  30.7 MB
__device__ float g_xi [NN * TT * K3];      // (n,t,k)  92.2 MB
__device__ float g_ha [NN * TT * HH];      // gru layer0 out
__device__ float g_hb [NN * TT * HH];      // gru layer1 out

__device__ __forceinline__ float sigmoidf_(float x) { return 1.0f / (1.0f + expf(-x)); }

// ---------------- degree / norm --------------------------------------------
__global__ void k_deg_init() {
    int i = blockIdx.x * blockDim.x + threadIdx.x;
    if (i < NN) g_deg[i] = 1.0f;           // self loop
}

__global__ void k_deg_edge(const int* __restrict__ ei) {
    int e = blockIdx.x * blockDim.x + threadIdx.x;
    if (e < NE) atomicAdd(&g_deg[ei[NE + e]], 1.0f);   // dst row
}

__global__ void k_dis() {
    int i = blockIdx.x * blockDim.x + threadIdx.x;
    if (i < NN) g_dis[i] = rsqrtf(g_deg[i]);
}

// agg init with self-loop term: agg[n,t,f] = x[t,n,f] * dis[n]^2
__global__ void k_agg_init(const float* __restrict__ x) {
    int idx = blockIdx.x * blockDim.x + threadIdx.x;
    if (idx >= NN * TT * FIN) return;
    int n = idx / (TT * FIN);
    int r = idx - n * (TT * FIN);
    int t = r >> 4, f = r & 15;
    float d = g_dis[n];
    g_agg[idx] = x[(t * NN + n) * FIN + f] * d * d;
}

// edge scatter: warp per edge, 6 x 32 covers the 192 (t,f) values
__global__ void k_edge_agg(const int* __restrict__ ei, const float* __restrict__ x) {
    int gt = blockIdx.x * blockDim.x + threadIdx.x;
    int e = gt >> 5, lane = gt & 31;
    if (e >= NE) return;
    int s = ei[e];
    int d = ei[NE + e];
    float c = g_dis[s] * g_dis[d];
    float* dstp = &g_agg[d * (TT * FIN)];
#pragma unroll
    for (int i = 0; i < 6; i++) {
        int k = lane + 32 * i;            // 0..191
        int t = k >> 4, f = k & 15;
        atomicAdd(&dstp[k], x[(t * NN + s) * FIN + f] * c);
    }
}

// ---------------- GCN matmul + relu : (NT,16) @ (16,64) --------------------
__global__ void k_gcn(const float* __restrict__ w, const float* __restrict__ b) {
    __shared__ float ws[FIN * HH];        // 4 KB
    __shared__ float ar[4][FIN];
    int tid = threadIdx.x;
    int row0 = blockIdx.x * 4;
    for (int i = tid; i < FIN * HH; i += 256) ws[i] = w[i];
    if (tid < 64) {
        int r = tid >> 4, f = tid & 15;
        int row = row0 + r;
        ar[r][f] = (row < NT) ? g_agg[row * FIN + f] : 0.0f;
    }
    __syncthreads();
    int r = tid >> 6, h = tid & 63;
    int row = row0 + r;
    if (row < NT) {
        float acc = b[h];
#pragma unroll
        for (int f = 0; f < FIN; f++) acc = fmaf(ar[r][f], ws[f * HH + h], acc);
        g_gcn[row * HH + h] = fmaxf(acc, 0.0f);
    }
}

// ---------------- input projection: xi = in @ w_ih^T + b_ih ----------------
// 192 threads; thread k owns output row k (w_ih[k][0..63] in registers).
// 48 rows per block (3 tiles of 16), activations broadcast from shared.
__global__ __launch_bounds__(192) void k_xi(const float* __restrict__ wg,
                                            const float* __restrict__ bg,
                                            int layer) {
    const float* in = (layer == 0) ? g_gcn : g_ha;
    int k = threadIdx.x;
    float w[64];
#pragma unroll
    for (int j = 0; j < 64; j++) w[j] = wg[k * 64 + j];
    float bk = bg[k];

    __shared__ __align__(16) float inS[16][64];   // 4 KB

    int rowbase0 = blockIdx.x * 48;
    for (int tile = 0; tile < 3; tile++) {
        int rowbase = rowbase0 + tile * 16;
        for (int i = k; i < 16 * 64; i += 192) {
            int r = i >> 6, j = i & 63;
            int row = rowbase + r;
            inS[r][j] = (row < NT) ? in[row * 64 + j] : 0.0f;
        }
        __syncthreads();
#pragma unroll 4
        for (int r = 0; r < 16; r++) {
            int row = rowbase + r;
            if (row < NT) {
                const float4* h4 = reinterpret_cast<const float4*>(&inS[r][0]);
                float a0 = 0.f, a1 = 0.f;
#pragma unroll
                for (int j = 0; j < 16; j++) {
                    float4 v = h4[j];
                    a0 = fmaf(v.x, w[4 * j + 0], a0);
                    a1 = fmaf(v.y, w[4 * j + 1], a1);
                    a0 = fmaf(v.z, w[4 * j + 2], a0);
                    a1 = fmaf(v.w, w[4 * j + 3], a1);
                }
                g_xi[row * K3 + k] = a0 + a1 + bk;
            }
        }
        __syncthreads();
    }
}

// ---------------- GRU recurrence -------------------------------------------
// Block: 192 threads, 32 nodes. Thread k owns gh[k]; w_hh[k][:] in registers.
// h double-buffered in shared; gh staged in shared for the gate combine.
__global__ __launch_bounds__(192) void k_rec(const float* __restrict__ wg,
                                             const float* __restrict__ bg,
                                             int layer) {
    float* outp = (layer == 0) ? g_ha : g_hb;
    int k = threadIdx.x;
    int node0 = blockIdx.x * 32;
    int nnb = NN - node0; if (nnb > 32) nnb = 32;

    float w[64];
#pragma unroll
    for (int j = 0; j < 64; j++) w[j] = wg[k * 64 + j];
    float bh = bg[k];

    __shared__ __align__(16) float hS[2][32][64];  // 16 KB
    __shared__ float ghS[32][K3];                  // 24 KB

    for (int i = k; i < 32 * 64; i += 192) ((float*)hS)[i] = 0.0f;
    __syncthreads();

    int cur = 0;
    for (int t = 0; t < TT; t++) {
        // phase 1: gh[m][k] = b_hh[k] + h[m] . w_hh[k]
        for (int m = 0; m < nnb; m++) {
            const float4* h4 = reinterpret_cast<const float4*>(&hS[cur][m][0]);
            float a0 = 0.f, a1 = 0.f;
#pragma unroll
            for (int j = 0; j < 16; j++) {
                float4 v = h4[j];
                a0 = fmaf(v.x, w[4 * j + 0], a0);
                a1 = fmaf(v.y, w[4 * j + 1], a1);
                a0 = fmaf(v.z, w[4 * j + 2], a0);
                a1 = fmaf(v.w, w[4 * j + 3], a1);
            }
            ghS[m][k] = a0 + a1 + bh;
        }
        __syncthreads();
        // phase 2: gates + state update
        for (int idx = k; idx < nnb * 64; idx += 192) {
            int m = idx >> 6, i = idx & 63;
            const float* xr = &g_xi[((node0 + m) * TT + t) * K3];
            float r  = sigmoidf_(xr[i]       + ghS[m][i]);
            float z  = sigmoidf_(xr[64 + i]  + ghS[m][64 + i]);
            float nv = tanhf   (xr[128 + i] + r * ghS[m][128 + i]);
            float hp = hS[cur][m][i];
            float hn = (1.0f - z) * nv + z * hp;
            hS[cur ^ 1][m][i] = hn;
            outp[((node0 + m) * TT + t) * HH + i] = hn;
        }
        __syncthreads();
        cur ^= 1;
    }
}

// ---------------- attention + fc + residual --------------------------------
__global__ void k_attn(const float* __restrict__ attn_w, const float* __restrict__ attn_b,
                       const float* __restrict__ fc_w,   const float* __restrict__ fc_b,
                       const float* __restrict__ x, float* __restrict__ out) {
    int gt = blockIdx.x * blockDim.x + threadIdx.x;
    int node = gt >> 5, lane = gt & 31;
    if (node >= NN) return;
    const float* hb = &g_hb[node * TT * HH];
    float aw0 = attn_w[lane], aw1 = attn_w[lane + 32];
    float s[TT];
#pragma unroll
    for (int t = 0; t < TT; t++) {
        float p = hb[t * HH + lane] * aw0 + hb[t * HH + lane + 32] * aw1;
#pragma unroll
        for (int o = 16; o > 0; o >>= 1) p += __shfl_xor_sync(0xffffffffu, p, o);
        s[t] = p + attn_b[0];
    }
    float mx = s[0];
#pragma unroll
    for (int t = 1; t < TT; t++) mx = fmaxf(mx, s[t]);
    float Z = 0.f;
#pragma unroll
    for (int t = 0; t < TT; t++) { s[t] = expf(s[t] - mx); Z += s[t]; }
    float inv = 1.0f / Z;
    float c0 = 0.f, c1 = 0.f;
#pragma unroll
    for (int t = 0; t < TT; t++) {
        float p = s[t] * inv;
        c0 = fmaf(p, hb[t * HH + lane], c0);
        c1 = fmaf(p, hb[t * HH + lane + 32], c1);
    }
    float res = c0 * fc_w[lane] + c1 * fc_w[lane + 32];
#pragma unroll
    for (int o = 16; o > 0; o >>= 1) res += __shfl_xor_sync(0xffffffffu, res, o);
    if (lane == 0) {
        float last = x[((TT - 1) * NN + node) * FIN + 0];
        out[node] = last + res + fc_b[0];
    }
}

// ---------------- launch ----------------------------------------------------
extern "C" void kernel_launch(void* const* d_in, const int* in_sizes, int n_in,
                              void* d_out, int out_size) {
    const float* x      = (const float*)d_in[0];
    const int*   ei     = (const int*)  d_in[1];
    const float* gcn_w  = (const float*)d_in[2];
    const float* gcn_b  = (const float*)d_in[3];
    const float* w_ih0  = (const float*)d_in[4];
    const float* w_hh0  = (const float*)d_in[5];
    const float* b_ih0  = (const float*)d_in[6];
    const float* b_hh0  = (const float*)d_in[7];
    const float* w_ih1  = (const float*)d_in[8];
    const float* w_hh1  = (const float*)d_in[9];
    const float* b_ih1  = (const float*)d_in[10];
    const float* b_hh1  = (const float*)d_in[11];
    const float* attn_w = (const float*)d_in[12];
    const float* attn_b = (const float*)d_in[13];
    const float* fc_w   = (const float*)d_in[14];
    const float* fc_b   = (const float*)d_in[15];
    float* out = (float*)d_out;

    k_deg_init<<<(NN + 255) / 256, 256>>>();
    k_deg_edge<<<(NE + 255) / 256, 256>>>(ei);
    k_dis<<<(NN + 255) / 256, 256>>>();
    k_agg_init<<<(NN * TT * FIN + 255) / 256, 256>>>(x);
    k_edge_agg<<<(NE * 32 + 255) / 256, 256>>>(ei, x);
    k_gcn<<<NT / 4, 256>>>(gcn_w, gcn_b);

    k_xi <<<(NT + 47) / 48, 192>>>(w_ih0, b_ih0, 0);
    k_rec<<<(NN + 31) / 32, 192>>>(w_hh0, b_hh0, 0);
    k_xi <<<(NT + 47) / 48, 192>>>(w_ih1, b_ih1, 1);
    k_rec<<<(NN + 31) / 32, 192>>>(w_hh1, b_hh1, 1);

    k_attn<<<(NN * 32 + 255) / 256, 256>>>(attn_w, attn_b, fc_w, fc_b, x, out);
}

// round 2
// speedup vs baseline: 1.6444x; 1.6444x over previous
#include <cuda_runtime.h>
#include <math.h>

#define NN 10000      // nodes
#define TT 12         // seq len
#define FIN 16        // in channels
#define HH 64         // hidden
#define K3 192        // 3*H
#define NE 160000     // edges
#define NT (NN*TT)    // 120000 rows

typedef unsigned long long ull;

// ---------------- scratch (device globals; no allocation allowed) ----------
__device__ float g_deg[NN];
__device__ float g_dis[NN];
__device__ float g_agg[NN * TT * FIN];     // (n,t,f)   7.68 MB
__device__ float g_gcn[NN * TT * HH];      // (n,t,h)  30.7 MB
__device__ float g_xi [NN * TT * K3];      // (n,t,k)  92.2 MB
__device__ float g_ha [NN * TT * HH];      // gru layer0 out
__device__ float g_hb [NN * TT * HH];      // gru layer1 out

// ---------------- packed fp32x2 FMA (SASS FFMA2; 2x fp32 throughput) -------
__device__ __forceinline__ ull ffma2(ull a, ull b, ull c) {
    ull d;
    asm("fma.rn.f32x2 %0, %1, %2, %3;" : "=l"(d) : "l"(a), "l"(b), "l"(c));
    return d;
}
__device__ __forceinline__ float hsum2(ull a) {
    return __uint_as_float((unsigned)a) + __uint_as_float((unsigned)(a >> 32));
}
__device__ __forceinline__ float tanh_fast(float x) {
    float y;
    asm("tanh.approx.f32 %0, %1;" : "=f"(y) : "f"(x));
    return y;
}
__device__ __forceinline__ float sigmoid_fast(float x) {
    return fmaf(0.5f, tanh_fast(0.5f * x), 0.5f);
}

// ---------------- degree / norm --------------------------------------------
__global__ void k_deg_init() {
    int i = blockIdx.x * blockDim.x + threadIdx.x;
    if (i < NN) g_deg[i] = 1.0f;           // self loop
}

__global__ void k_deg_edge(const int* __restrict__ ei) {
    int e = blockIdx.x * blockDim.x + threadIdx.x;
    if (e < NE) atomicAdd(&g_deg[ei[NE + e]], 1.0f);   // dst row
}

__global__ void k_dis() {
    int i = blockIdx.x * blockDim.x + threadIdx.x;
    if (i < NN) g_dis[i] = rsqrtf(g_deg[i]);
}

// agg init with self-loop term: agg[n,t,f] = x[t,n,f] * dis[n]^2
__global__ void k_agg_init(const float* __restrict__ x) {
    int idx = blockIdx.x * blockDim.x + threadIdx.x;
    if (idx >= NN * TT * FIN) return;
    int n = idx / (TT * FIN);
    int r = idx - n * (TT * FIN);
    int t = r >> 4, f = r & 15;
    float d = g_dis[n];
    g_agg[idx] = x[(t * NN + n) * FIN + f] * d * d;
}

// edge scatter: warp per edge, 6 x 32 covers the 192 (t,f) values
__global__ void k_edge_agg(const int* __restrict__ ei, const float* __restrict__ x) {
    int gt = blockIdx.x * blockDim.x + threadIdx.x;
    int e = gt >> 5, lane = gt & 31;
    if (e >= NE) return;
    int s = ei[e];
    int d = ei[NE + e];
    float c = g_dis[s] * g_dis[d];
    float* dstp = &g_agg[d * (TT * FIN)];
#pragma unroll
    for (int i = 0; i < 6; i++) {
        int k = lane + 32 * i;            // 0..191
        int t = k >> 4, f = k & 15;
        atomicAdd(&dstp[k], x[(t * NN + s) * FIN + f] * c);
    }
}

// ---------------- GCN matmul + relu : (NT,16) @ (16,64) --------------------
__global__ void k_gcn(const float* __restrict__ w, const float* __restrict__ b) {
    __shared__ float ws[FIN * HH];        // 4 KB
    __shared__ float ar[4][FIN];
    int tid = threadIdx.x;
    int row0 = blockIdx.x * 4;
    for (int i = tid; i < FIN * HH; i += 256) ws[i] = w[i];
    if (tid < 64) {
        int r = tid >> 4, f = tid & 15;
        int row = row0 + r;
        ar[r][f] = (row < NT) ? g_agg[row * FIN + f] : 0.0f;
    }
    __syncthreads();
    int r = tid >> 6, h = tid & 63;
    int row = row0 + r;
    if (row < NT) {
        float acc = b[h];
#pragma unroll
        for (int f = 0; f < FIN; f++) acc = fmaf(ar[r][f], ws[f * HH + h], acc);
        g_gcn[row * HH + h] = fmaxf(acc, 0.0f);
    }
}

// ---------------- input projection: xi = in @ w_ih^T + b_ih ----------------
// 192 threads; thread k owns output row k (w_ih[k][0..63] packed in f32x2 regs).
// 48 rows per block (3 tiles of 16); NT = 2500 * 48 exactly (no bounds checks).
__global__ __launch_bounds__(192) void k_xi(const float* __restrict__ wg,
                                            const float* __restrict__ bg,
                                            int layer) {
    const float* in = (layer == 0) ? g_gcn : g_ha;
    int k = threadIdx.x;
    ull w2[32];
    {
        const ulonglong2* wq = reinterpret_cast<const ulonglong2*>(wg + (size_t)k * 64);
#pragma unroll
        for (int j = 0; j < 16; j++) { ulonglong2 q = wq[j]; w2[2 * j] = q.x; w2[2 * j + 1] = q.y; }
    }
    float bk = bg[k];

    __shared__ __align__(16) float inS[16][64];   // 4 KB

    int rowbase0 = blockIdx.x * 48;
    for (int tile = 0; tile < 3; tile++) {
        int rowbase = rowbase0 + tile * 16;
        // vectorized fill: 16*64 floats = 256 float4
        {
            const float4* src = reinterpret_cast<const float4*>(in + (size_t)rowbase * 64);
            float4* dst = reinterpret_cast<float4*>(&inS[0][0]);
            for (int i = k; i < 256; i += 192) dst[i] = src[i];
        }
        __syncthreads();
#pragma unroll 2
        for (int r = 0; r < 16; r++) {
            const ulonglong2* h2 = reinterpret_cast<const ulonglong2*>(&inS[r][0]);
            ull a0 = 0ull, a1 = 0ull;
#pragma unroll
            for (int j = 0; j < 16; j++) {
                ulonglong2 v = h2[j];
                a0 = ffma2(v.x, w2[2 * j], a0);
                a1 = ffma2(v.y, w2[2 * j + 1], a1);
            }
            g_xi[(size_t)(rowbase + r) * K3 + k] = hsum2(a0) + hsum2(a1) + bk;
        }
        __syncthreads();
    }
}

// ---------------- GRU recurrence -------------------------------------------
// Block: 192 threads, 32 nodes. Thread k owns gh[k]; w_hh[k][:] in f32x2 regs.
// h double-buffered in shared; gh staged in shared for the gate combine.
__global__ __launch_bounds__(192) void k_rec(const float* __restrict__ wg,
                                             const float* __restrict__ bg,
                                             int layer) {
    float* outp = (layer == 0) ? g_ha : g_hb;
    int k = threadIdx.x;
    int node0 = blockIdx.x * 32;
    int nnb = NN - node0; if (nnb > 32) nnb = 32;

    ull w2[32];
    {
        const ulonglong2* wq = reinterpret_cast<const ulonglong2*>(wg + (size_t)k * 64);
#pragma unroll
        for (int j = 0; j < 16; j++) { ulonglong2 q = wq[j]; w2[2 * j] = q.x; w2[2 * j + 1] = q.y; }
    }
    float bh = bg[k];

    __shared__ __align__(16) float hS[2][32][64];  // 16 KB
    __shared__ float ghS[32][K3];                  // 24 KB

    for (int i = k; i < 32 * 64; i += 192) ((float*)hS)[i] = 0.0f;
    __syncthreads();

    int cur = 0;
    for (int t = 0; t < TT; t++) {
        // phase 1: gh[m][k] = b_hh[k] + h[m] . w_hh[k]   (f32x2 packed)
#pragma unroll 2
        for (int m = 0; m < nnb; m++) {
            const ulonglong2* h2 = reinterpret_cast<const ulonglong2*>(&hS[cur][m][0]);
            ull a0 = 0ull, a1 = 0ull;
#pragma unroll
            for (int j = 0; j < 16; j++) {
                ulonglong2 v = h2[j];
                a0 = ffma2(v.x, w2[2 * j], a0);
                a1 = ffma2(v.y, w2[2 * j + 1], a1);
            }
            ghS[m][k] = hsum2(a0) + hsum2(a1) + bh;
        }
        __syncthreads();
        // phase 2: gates + state update
        for (int idx = k; idx < nnb * 64; idx += 192) {
            int m = idx >> 6, i = idx & 63;
            const float* xr = &g_xi[((size_t)(node0 + m) * TT + t) * K3];
            float r  = sigmoid_fast(xr[i]       + ghS[m][i]);
            float z  = sigmoid_fast(xr[64 + i]  + ghS[m][64 + i]);
            float nv = tanh_fast   (xr[128 + i] + r * ghS[m][128 + i]);
            float hp = hS[cur][m][i];
            float hn = (1.0f - z) * nv + z * hp;
            hS[cur ^ 1][m][i] = hn;
            outp[((size_t)(node0 + m) * TT + t) * HH + i] = hn;
        }
        __syncthreads();
        cur ^= 1;
    }
}

// ---------------- attention + fc + residual --------------------------------
__global__ void k_attn(const float* __restrict__ attn_w, const float* __restrict__ attn_b,
                       const float* __restrict__ fc_w,   const float* __restrict__ fc_b,
                       const float* __restrict__ x, float* __restrict__ out) {
    int gt = blockIdx.x * blockDim.x + threadIdx.x;
    int node = gt >> 5, lane = gt & 31;
    if (node >= NN) return;
    const float* hb = &g_hb[(size_t)node * TT * HH];
    float aw0 = attn_w[lane], aw1 = attn_w[lane + 32];
    float s[TT];
#pragma unroll
    for (int t = 0; t < TT; t++) {
        float p = hb[t * HH + lane] * aw0 + hb[t * HH + lane + 32] * aw1;
#pragma unroll
        for (int o = 16; o > 0; o >>= 1) p += __shfl_xor_sync(0xffffffffu, p, o);
        s[t] = p + attn_b[0];
    }
    float mx = s[0];
#pragma unroll
    for (int t = 1; t < TT; t++) mx = fmaxf(mx, s[t]);
    float Z = 0.f;
#pragma unroll
    for (int t = 0; t < TT; t++) { s[t] = expf(s[t] - mx); Z += s[t]; }
    float inv = 1.0f / Z;
    float c0 = 0.f, c1 = 0.f;
#pragma unroll
    for (int t = 0; t < TT; t++) {
        float p = s[t] * inv;
        c0 = fmaf(p, hb[t * HH + lane], c0);
        c1 = fmaf(p, hb[t * HH + lane + 32], c1);
    }
    float res = c0 * fc_w[lane] + c1 * fc_w[lane + 32];
#pragma unroll
    for (int o = 16; o > 0; o >>= 1) res += __shfl_xor_sync(0xffffffffu, res, o);
    if (lane == 0) {
        float last = x[((TT - 1) * NN + node) * FIN + 0];
        out[node] = last + res + fc_b[0];
    }
}

// ---------------- launch ----------------------------------------------------
extern "C" void kernel_launch(void* const* d_in, const int* in_sizes, int n_in,
                              void* d_out, int out_size) {
    const float* x      = (const float*)d_in[0];
    const int*   ei     = (const int*)  d_in[1];
    const float* gcn_w  = (const float*)d_in[2];
    const float* gcn_b  = (const float*)d_in[3];
    const float* w_ih0  = (const float*)d_in[4];
    const float* w_hh0  = (const float*)d_in[5];
    const float* b_ih0  = (const float*)d_in[6];
    const float* b_hh0  = (const float*)d_in[7];
    const float* w_ih1  = (const float*)d_in[8];
    const float* w_hh1  = (const float*)d_in[9];
    const float* b_ih1  = (const float*)d_in[10];
    const float* b_hh1  = (const float*)d_in[11];
    const float* attn_w = (const float*)d_in[12];
    const float* attn_b = (const float*)d_in[13];
    const float* fc_w   = (const float*)d_in[14];
    const float* fc_b   = (const float*)d_in[15];
    float* out = (float*)d_out;

    k_deg_init<<<(NN + 255) / 256, 256>>>();
    k_deg_edge<<<(NE + 255) / 256, 256>>>(ei);
    k_dis<<<(NN + 255) / 256, 256>>>();
    k_agg_init<<<(NN * TT * FIN + 255) / 256, 256>>>(x);
    k_edge_agg<<<(NE * 32 + 255) / 256, 256>>>(ei, x);
    k_gcn<<<NT / 4, 256>>>(gcn_w, gcn_b);

    k_xi <<<NT / 48, 192>>>(w_ih0, b_ih0, 0);
    k_rec<<<(NN + 31) / 32, 192>>>(w_hh0, b_hh0, 0);
    k_xi <<<NT / 48, 192>>>(w_ih1, b_ih1, 1);
    k_rec<<<(NN + 31) / 32, 192>>>(w_hh1, b_hh1, 1);

    k_attn<<<(NN * 32 + 255) / 256, 256>>>(attn_w, attn_b, fc_w, fc_b, x, out);
}

// round 3
// speedup vs baseline: 2.3383x; 1.4220x over previous
#include <cuda_runtime.h>
#include <math.h>

#define NN 10000      // nodes
#define TT 12         // seq len
#define FIN 16        // in channels
#define HH 64         // hidden
#define K3 192        // 3*H
#define NE 160000     // edges
#define NT (NN*TT)    // 120000 rows
#define NPB 68        // nodes per block in fused rec (148 blocks = 1 wave)

typedef unsigned long long ull;

// ---------------- scratch (device globals; no allocation allowed) ----------
__device__ float g_deg[NN];
__device__ float g_dis[NN];
__device__ float g_agg[NN * TT * FIN];     // (n,t,f)   7.68 MB
__device__ float g_gcn[NN * TT * HH];      // (n,t,h)  30.7 MB
__device__ float g_ha [NN * TT * HH];      // gru layer0 out
__device__ float g_hb [NN * TT * HH];      // gru layer1 out

// ---------------- packed fp32x2 FMA (SASS FFMA2; 2x fp32 throughput) -------
__device__ __forceinline__ ull ffma2(ull a, ull b, ull c) {
    ull d;
    asm("fma.rn.f32x2 %0, %1, %2, %3;" : "=l"(d) : "l"(a), "l"(b), "l"(c));
    return d;
}
__device__ __forceinline__ float hsum2(ull a) {
    return __uint_as_float((unsigned)a) + __uint_as_float((unsigned)(a >> 32));
}
__device__ __forceinline__ float tanh_fast(float x) {
    float y;
    asm("tanh.approx.f32 %0, %1;" : "=f"(y) : "f"(x));
    return y;
}
__device__ __forceinline__ float sigmoid_fast(float x) {
    return fmaf(0.5f, tanh_fast(0.5f * x), 0.5f);
}

// ---------------- degree / norm --------------------------------------------
__global__ void k_deg_init() {
    int i = blockIdx.x * blockDim.x + threadIdx.x;
    if (i < NN) g_deg[i] = 1.0f;           // self loop
}

__global__ void k_deg_edge(const int* __restrict__ ei) {
    int e = blockIdx.x * blockDim.x + threadIdx.x;
    if (e < NE) atomicAdd(&g_deg[ei[NE + e]], 1.0f);   // dst row
}

__global__ void k_dis() {
    int i = blockIdx.x * blockDim.x + threadIdx.x;
    if (i < NN) g_dis[i] = rsqrtf(g_deg[i]);
}

// agg init with self-loop term: agg[n,t,f] = x[t,n,f] * dis[n]^2
__global__ void k_agg_init(const float* __restrict__ x) {
    int idx = blockIdx.x * blockDim.x + threadIdx.x;
    if (idx >= NN * TT * FIN) return;
    int n = idx / (TT * FIN);
    int r = idx - n * (TT * FIN);
    int t = r >> 4, f = r & 15;
    float d = g_dis[n];
    g_agg[idx] = x[(t * NN + n) * FIN + f] * d * d;
}

// edge scatter: warp per edge; 192 floats = 48 float4 groups, red.v4
__global__ void k_edge_agg(const int* __restrict__ ei, const float* __restrict__ x) {
    int gt = blockIdx.x * blockDim.x + threadIdx.x;
    int e = gt >> 5, lane = gt & 31;
    if (e >= NE) return;
    int s = ei[e];
    int d = ei[NE + e];
    float c = g_dis[s] * g_dis[d];
    const float4* x4 = reinterpret_cast<const float4*>(x);
    float4* dst4 = reinterpret_cast<float4*>(&g_agg[(size_t)d * (TT * FIN)]);
#pragma unroll
    for (int g = lane; g < 48; g += 32) {
        int t = g >> 2, f4 = g & 3;
        float4 v = x4[((size_t)t * NN + s) * 4 + f4];
        asm volatile("red.global.add.v4.f32 [%0], {%1, %2, %3, %4};"
                     :: "l"(dst4 + g), "f"(v.x * c), "f"(v.y * c), "f"(v.z * c), "f"(v.w * c)
                     : "memory");
    }
}

// ---------------- GCN matmul + relu : (NT,16) @ (16,64) --------------------
__global__ void k_gcn(const float* __restrict__ w, const float* __restrict__ b) {
    __shared__ float ws[FIN * HH];        // 4 KB
    __shared__ float ar[4][FIN];
    int tid = threadIdx.x;
    int row0 = blockIdx.x * 4;
    for (int i = tid; i < FIN * HH; i += 256) ws[i] = w[i];
    if (tid < 64) {
        int r = tid >> 4, f = tid & 15;
        int row = row0 + r;
        ar[r][f] = (row < NT) ? g_agg[row * FIN + f] : 0.0f;
    }
    __syncthreads();
    int r = tid >> 6, h = tid & 63;
    int row = row0 + r;
    if (row < NT) {
        float acc = b[h];
#pragma unroll
        for (int f = 0; f < FIN; f++) acc = fmaf(ar[r][f], ws[f * HH + h], acc);
        g_gcn[row * HH + h] = fmaxf(acc, 0.0f);
    }
}

// ---------------- fused GRU layer: xi + recurrence in one kernel -----------
// 384 threads: warps 0-5 hold w_ih rows (compute gx), warps 6-11 hold w_hh
// rows (compute gh). 68 nodes per block, grid=148 (exactly one wave).
// Per timestep: stage input tile -> both projections (f32x2) -> gates.
// No g_xi round-trip through DRAM.
struct RecSmem {
    float hS[2][NPB][64];   // 34.8 KB  (double-buffered hidden state)
    float gx[NPB][192];     // 52.2 KB
    float gh[NPB][192];     // 52.2 KB
    float inS[NPB][64];     // 17.4 KB  (staged input rows for current t)
};

__global__ __launch_bounds__(384) void k_rec_fused(
    const float* __restrict__ wih, const float* __restrict__ bihp,
    const float* __restrict__ whh, const float* __restrict__ bhhp,
    int layer)
{
    const float* in = layer ? g_ha : g_gcn;
    float* outp     = layer ? g_hb : g_ha;
    int tid = threadIdx.x;
    bool is_ih = tid < 192;
    int k = is_ih ? tid : tid - 192;

    const float* wsrc = is_ih ? wih : whh;
    ull w2[32];
    {
        const ulonglong2* wq = reinterpret_cast<const ulonglong2*>(wsrc + (size_t)k * 64);
#pragma unroll
        for (int j = 0; j < 16; j++) { ulonglong2 q = wq[j]; w2[2 * j] = q.x; w2[2 * j + 1] = q.y; }
    }
    float bias = is_ih ? bihp[k] : bhhp[k];

    int node0 = blockIdx.x * NPB;
    int nnb = NN - node0; if (nnb > NPB) nnb = NPB;

    extern __shared__ __align__(16) char smraw[];
    RecSmem* S = reinterpret_cast<RecSmem*>(smraw);
    float* dstS = is_ih ? &S->gx[0][0] : &S->gh[0][0];

    for (int i = tid; i < 2 * NPB * 64; i += 384) ((float*)S->hS)[i] = 0.0f;

    int cur = 0;
    const float4* in4 = reinterpret_cast<const float4*>(in);
    for (int t = 0; t < TT; t++) {
        // stage input rows (n, t) for the 68 nodes
        for (int i4 = tid; i4 < nnb * 16; i4 += 384) {
            int m = i4 >> 4, j = i4 & 15;
            reinterpret_cast<float4*>(S->inS[m])[j] =
                in4[((size_t)(node0 + m) * TT + t) * 16 + j];
        }
        __syncthreads();
        // phase 1: gx[m][k] = in[m].w_ih[k]+b_ih[k] ; gh[m][k] = h[m].w_hh[k]+b_hh[k]
        const float* base = is_ih ? &S->inS[0][0] : &S->hS[cur][0][0];
        for (int m = 0; m < nnb; m++) {
            const ulonglong2* s2 = reinterpret_cast<const ulonglong2*>(base + m * 64);
            ull a0 = 0ull, a1 = 0ull;
#pragma unroll
            for (int j = 0; j < 16; j++) {
                ulonglong2 v = s2[j];
                a0 = ffma2(v.x, w2[2 * j], a0);
                a1 = ffma2(v.y, w2[2 * j + 1], a1);
            }
            dstS[m * 192 + k] = hsum2(a0) + hsum2(a1) + bias;
        }
        __syncthreads();
        // phase 2: gates + state update
        for (int idx = tid; idx < nnb * 64; idx += 384) {
            int m = idx >> 6, i = idx & 63;
            float r  = sigmoid_fast(S->gx[m][i]       + S->gh[m][i]);
            float z  = sigmoid_fast(S->gx[m][64 + i]  + S->gh[m][64 + i]);
            float nv = tanh_fast   (S->gx[m][128 + i] + r * S->gh[m][128 + i]);
            float hp = S->hS[cur][m][i];
            float hn = (1.0f - z) * nv + z * hp;
            S->hS[cur ^ 1][m][i] = hn;
            outp[((size_t)(node0 + m) * TT + t) * HH + i] = hn;
        }
        cur ^= 1;
        // no 3rd sync needed: next-iter inS overwrite / gx,gh overwrite are
        // ordered against this phase's readers by the next loop's syncthreads.
    }
}

// ---------------- attention + fc + residual --------------------------------
__global__ void k_attn(const float* __restrict__ attn_w, const float* __restrict__ attn_b,
                       const float* __restrict__ fc_w,   const float* __restrict__ fc_b,
                       const float* __restrict__ x, float* __restrict__ out) {
    int gt = blockIdx.x * blockDim.x + threadIdx.x;
    int node = gt >> 5, lane = gt & 31;
    if (node >= NN) return;
    const float* hb = &g_hb[(size_t)node * TT * HH];
    float aw0 = attn_w[lane], aw1 = attn_w[lane + 32];
    float s[TT];
#pragma unroll
    for (int t = 0; t < TT; t++) {
        float p = hb[t * HH + lane] * aw0 + hb[t * HH + lane + 32] * aw1;
#pragma unroll
        for (int o = 16; o > 0; o >>= 1) p += __shfl_xor_sync(0xffffffffu, p, o);
        s[t] = p + attn_b[0];
    }
    float mx = s[0];
#pragma unroll
    for (int t = 1; t < TT; t++) mx = fmaxf(mx, s[t]);
    float Z = 0.f;
#pragma unroll
    for (int t = 0; t < TT; t++) { s[t] = expf(s[t] - mx); Z += s[t]; }
    float inv = 1.0f / Z;
    float c0 = 0.f, c1 = 0.f;
#pragma unroll
    for (int t = 0; t < TT; t++) {
        float p = s[t] * inv;
        c0 = fmaf(p, hb[t * HH + lane], c0);
        c1 = fmaf(p, hb[t * HH + lane + 32], c1);
    }
    float res = c0 * fc_w[lane] + c1 * fc_w[lane + 32];
#pragma unroll
    for (int o = 16; o > 0; o >>= 1) res += __shfl_xor_sync(0xffffffffu, res, o);
    if (lane == 0) {
        float last = x[((TT - 1) * NN + node) * FIN + 0];
        out[node] = last + res + fc_b[0];
    }
}

// ---------------- launch ----------------------------------------------------
extern "C" void kernel_launch(void* const* d_in, const int* in_sizes, int n_in,
                              void* d_out, int out_size) {
    const float* x      = (const float*)d_in[0];
    const int*   ei     = (const int*)  d_in[1];
    const float* gcn_w  = (const float*)d_in[2];
    const float* gcn_b  = (const float*)d_in[3];
    const float* w_ih0  = (const float*)d_in[4];
    const float* w_hh0  = (const float*)d_in[5];
    const float* b_ih0  = (const float*)d_in[6];
    const float* b_hh0  = (const float*)d_in[7];
    const float* w_ih1  = (const float*)d_in[8];
    const float* w_hh1  = (const float*)d_in[9];
    const float* b_ih1  = (const float*)d_in[10];
    const float* b_hh1  = (const float*)d_in[11];
    const float* attn_w = (const float*)d_in[12];
    const float* attn_b = (const float*)d_in[13];
    const float* fc_w   = (const float*)d_in[14];
    const float* fc_b   = (const float*)d_in[15];
    float* out = (float*)d_out;

    static const int REC_SMEM = (int)sizeof(RecSmem);
    cudaFuncSetAttribute(k_rec_fused, cudaFuncAttributeMaxDynamicSharedMemorySize, REC_SMEM);

    k_deg_init<<<(NN + 255) / 256, 256>>>();
    k_deg_edge<<<(NE + 255) / 256, 256>>>(ei);
    k_dis<<<(NN + 255) / 256, 256>>>();
    k_agg_init<<<(NN * TT * FIN + 255) / 256, 256>>>(x);
    k_edge_agg<<<(NE * 32 + 255) / 256, 256>>>(ei, x);
    k_gcn<<<NT / 4, 256>>>(gcn_w, gcn_b);

    k_rec_fused<<<(NN + NPB - 1) / NPB, 384, REC_SMEM>>>(w_ih0, b_ih0, w_hh0, b_hh0, 0);
    k_rec_fused<<<(NN + NPB - 1) / NPB, 384, REC_SMEM>>>(w_ih1, b_ih1, w_hh1, b_hh1, 1);

    k_attn<<<(NN * 32 + 255) / 256, 256>>>(attn_w, attn_b, fc_w, fc_b, x, out);
}

// round 5
// speedup vs baseline: 4.1171x; 1.7608x over previous
#include <cuda_runtime.h>
#include <cuda_bf16.h>
#include <math.h>

#define NN 10000      // nodes
#define TT 12         // seq len
#define FIN 16        // in channels
#define HH 64         // hidden
#define K3 192        // 3*H
#define NE 160000     // edges
#define NT (NN*TT)    // 120000 rows
#define MB 80         // nodes per block (10000 = 125 * 80)
#define GRID_REC 125

typedef unsigned int u32;
typedef unsigned long long u64;

// ---------------- scratch (device globals; no allocation allowed) ----------
__device__ float g_deg[NN];
__device__ float g_dis[NN];
__device__ float g_agg[NN * TT * FIN];
__device__ float g_gcn[NN * TT * HH];
__device__ float g_ha [NN * TT * HH];
__device__ float g_hb [NN * TT * HH];

// ---------------- helpers ----------------------------------------------------
__device__ __forceinline__ float tanh_fast(float x) {
    float y; asm("tanh.approx.f32 %0, %1;" : "=f"(y) : "f"(x)); return y;
}
__device__ __forceinline__ float sigmoid_fast(float x) {
    return fmaf(0.5f, tanh_fast(0.5f * x), 0.5f);
}
__device__ __forceinline__ u32 pack2(__nv_bfloat16 a, __nv_bfloat16 b) {
    return (u32)__bfloat16_as_ushort(a) | ((u32)__bfloat16_as_ushort(b) << 16);
}
__device__ __forceinline__ void split_bf16(float v, __nv_bfloat16& hi, __nv_bfloat16& lo) {
    hi = __float2bfloat16(v);
    lo = __float2bfloat16(v - __bfloat162float(hi));
}
// m16n8k16 row.col bf16 MMA, fp32 accumulate
__device__ __forceinline__ void mma16816(float* c, const u32* a, u32 b0, u32 b1) {
    asm volatile(
        "mma.sync.aligned.m16n8k16.row.col.f32.bf16.bf16.f32 "
        "{%0,%1,%2,%3}, {%4,%5,%6,%7}, {%8,%9}, {%0,%1,%2,%3};"
        : "+f"(c[0]), "+f"(c[1]), "+f"(c[2]), "+f"(c[3])
        : "r"(a[0]), "r"(a[1]), "r"(a[2]), "r"(a[3]), "r"(b0), "r"(b1));
}

// ---------------- degree / norm --------------------------------------------
__global__ void k_deg_init() {
    int i = blockIdx.x * blockDim.x + threadIdx.x;
    if (i < NN) g_deg[i] = 1.0f;
}
__global__ void k_deg_edge(const int* __restrict__ ei) {
    int e = blockIdx.x * blockDim.x + threadIdx.x;
    if (e < NE) atomicAdd(&g_deg[ei[NE + e]], 1.0f);
}
__global__ void k_dis() {
    int i = blockIdx.x * blockDim.x + threadIdx.x;
    if (i < NN) g_dis[i] = rsqrtf(g_deg[i]);
}
__global__ void k_agg_init(const float* __restrict__ x) {
    int idx = blockIdx.x * blockDim.x + threadIdx.x;
    if (idx >= NN * TT * FIN) return;
    int n = idx / (TT * FIN);
    int r = idx - n * (TT * FIN);
    int t = r >> 4, f = r & 15;
    float d = g_dis[n];
    g_agg[idx] = x[(t * NN + n) * FIN + f] * d * d;
}
__global__ void k_edge_agg(const int* __restrict__ ei, const float* __restrict__ x) {
    int gt = blockIdx.x * blockDim.x + threadIdx.x;
    int e = gt >> 5, lane = gt & 31;
    if (e >= NE) return;
    int s = ei[e];
    int d = ei[NE + e];
    float c = g_dis[s] * g_dis[d];
    const float4* x4 = reinterpret_cast<const float4*>(x);
    float4* dst4 = reinterpret_cast<float4*>(&g_agg[(size_t)d * (TT * FIN)]);
#pragma unroll
    for (int g = lane; g < 48; g += 32) {
        int t = g >> 2, f4 = g & 3;
        float4 v = x4[((size_t)t * NN + s) * 4 + f4];
        asm volatile("red.global.add.v4.f32 [%0], {%1, %2, %3, %4};"
                     :: "l"(dst4 + g), "f"(v.x * c), "f"(v.y * c), "f"(v.z * c), "f"(v.w * c)
                     : "memory");
    }
}

// ---------------- GCN matmul + relu : (NT,16) @ (16,64) --------------------
__global__ void k_gcn(const float* __restrict__ w, const float* __restrict__ b) {
    __shared__ float ws[FIN * HH];
    __shared__ float ar[4][FIN];
    int tid = threadIdx.x;
    int row0 = blockIdx.x * 4;
    for (int i = tid; i < FIN * HH; i += 256) ws[i] = w[i];
    if (tid < 64) {
        int r = tid >> 4, f = tid & 15;
        ar[r][f] = g_agg[(row0 + r) * FIN + f];
    }
    __syncthreads();
    int r = tid >> 6, h = tid & 63;
    int row = row0 + r;
    float acc = b[h];
#pragma unroll
    for (int f = 0; f < FIN; f++) acc = fmaf(ar[r][f], ws[f * HH + h], acc);
    g_gcn[row * HH + h] = fmaxf(acc, 0.0f);
}

// ---------------- HMMA GRU layer --------------------------------------------
// Block: 80 nodes, 384 threads (12 warps). Per timestep, D[80x256] computed by
// warp-level m16n8k16 bf16 MMAs with 3-term hi/lo split (fp32-accurate):
//   warps 0-7 : r|z cols (16 each), A = [X|H] K=128
//   warps 8-9 : xn cols (32 each),  A = X  K=64
//   warps 10-11: hn cols (32 each), A = H  K=64
// A tile: bf16 hi/lo, 256B rows [X(128B)|H(128B)], XOR-swizzled for
// conflict-free fragment loads. Weights = persistent register B-fragments.
#define OFF_AHI 0
#define OFF_ALO 20480
#define OFF_GRZ 40960      // fp32 [80][128], swizzled
#define OFF_GX  81920      // fp32 [80][64]
#define OFF_GH  102400
#define OFF_HS  122880     // fp32 h state [80][64], plain
#define OFF_B   143360     // biases: brz[128], bxn[64], bhn[64]
#define REC_SMEM 144384

template<int KKS, int NTS>
__device__ __forceinline__ void mma_m_tile(
    const char* AHI, const char* ALO, const u32* bh, const u32* bl,
    float* acc, int rb0, int rb1, int aoff, int swA, int tg)
{
#pragma unroll
    for (int q = 0; q < NTS * 4; q++) acc[q] = 0.0f;
#pragma unroll
    for (int kk = 0; kk < KKS; kk++) {
        int c0 = aoff + ((kk * 32 + 4 * tg) ^ swA);
        int c2 = aoff + ((kk * 32 + 16 + 4 * tg) ^ swA);
        u32 ah[4], al[4];
        ah[0] = *(const u32*)(AHI + rb0 + c0); ah[1] = *(const u32*)(AHI + rb1 + c0);
        ah[2] = *(const u32*)(AHI + rb0 + c2); ah[3] = *(const u32*)(AHI + rb1 + c2);
        al[0] = *(const u32*)(ALO + rb0 + c0); al[1] = *(const u32*)(ALO + rb1 + c0);
        al[2] = *(const u32*)(ALO + rb0 + c2); al[3] = *(const u32*)(ALO + rb1 + c2);
#pragma unroll
        for (int nt = 0; nt < NTS; nt++) {
            int f = kk * NTS + nt;
            mma16816(acc + nt * 4, ah, bh[2 * f], bh[2 * f + 1]);
            mma16816(acc + nt * 4, ah, bl[2 * f], bl[2 * f + 1]);
            mma16816(acc + nt * 4, al, bh[2 * f], bh[2 * f + 1]);
        }
    }
}

__global__ __launch_bounds__(384, 1) void k_rec_mma(
    const float* __restrict__ wih, const float* __restrict__ whh,
    const float* __restrict__ bih, const float* __restrict__ bhh, int layer)
{
    const float* in  = layer ? g_ha : g_gcn;
    float*      outp = layer ? g_hb : g_ha;
    extern __shared__ __align__(16) char sm[];
    char* AHI = sm + OFF_AHI;
    char* ALO = sm + OFF_ALO;
    char* GRZ = sm + OFF_GRZ;
    char* GX  = sm + OFF_GX;
    char* GH  = sm + OFF_GH;
    float* hS   = (float*)(sm + OFF_HS);
    float* bias = (float*)(sm + OFF_B);

    int tid = threadIdx.x, wid = tid >> 5, lid = tid & 31;
    int g = lid >> 2, tg = lid & 3;
    int node0 = blockIdx.x * MB;

    // biases: brz[0..127]=bih+bhh, [128..191]=bih_n, [192..255]=bhh_n
    if (tid < 128) bias[tid] = bih[tid] + bhh[tid];
    else if (tid < 192) bias[tid] = bih[tid];
    else if (tid < 256) bias[tid] = bhh[tid - 64];

    // zero A tiles (incl. H region => h0 = 0) and fp32 h state
    {
        uint4 z = make_uint4(0, 0, 0, 0);
        for (int i = tid; i < 2560; i += 384) {
            ((uint4*)AHI)[i] = z;
            ((uint4*)ALO)[i] = z;
        }
        for (int i = tid; i < MB * 64; i += 384) hS[i] = 0.0f;
    }

    bool is_rz = wid < 8;
    int role = is_rz ? 0 : (wid < 10 ? 1 : 2);

    // persistent B fragments (hi/lo), 16 (kk,nt) slots x 2 regs
    u32 bh[32], bl[32];
#pragma unroll
    for (int f = 0; f < 16; f++) {
        int kk = is_rz ? (f >> 1) : (f >> 2);
        int nt = is_rz ? (f & 1)  : (f & 3);
        int nrow;
        if (role == 0)      nrow = wid * 16 + nt * 8 + g;
        else if (role == 1) nrow = 128 + (wid - 8) * 32 + nt * 8 + g;
        else                nrow = 128 + (wid - 10) * 32 + nt * 8 + g;
#pragma unroll
        for (int r = 0; r < 2; r++) {
            int k = kk * 16 + tg * 2 + r * 8;
            float w0, w1;
            if (role == 0) {
                if (k < 64) { w0 = wih[nrow * 64 + k];      w1 = wih[nrow * 64 + k + 1]; }
                else        { w0 = whh[nrow * 64 + k - 64]; w1 = whh[nrow * 64 + k - 63]; }
            } else if (role == 1) {
                w0 = wih[nrow * 64 + k]; w1 = wih[nrow * 64 + k + 1];
            } else {
                w0 = whh[nrow * 64 + k]; w1 = whh[nrow * 64 + k + 1];
            }
            __nv_bfloat16 h0, l0, h1, l1;
            split_bf16(w0, h0, l0);
            split_bf16(w1, h1, l1);
            bh[2 * f + r] = pack2(h0, h1);
            bl[2 * f + r] = pack2(l0, l1);
        }
    }

    int aoff = (role == 2) ? 128 : 0;   // hn warps read H half of A tile
    int swA = g << 4;
    const float4* in4 = reinterpret_cast<const float4*>(in);

    for (int t = 0; t < TT; t++) {
        // stage X(t): fp32 -> bf16 hi/lo into X half of A tile (swizzled)
        for (int i = tid; i < MB * 16; i += 384) {
            int m = i >> 4, j = i & 15;
            float4 v = in4[((size_t)(node0 + m) * TT + t) * 16 + j];
            __nv_bfloat16 a0, b0, a1, b1, a2, b2, a3, b3;
            split_bf16(v.x, a0, b0); split_bf16(v.y, a1, b1);
            split_bf16(v.z, a2, b2); split_bf16(v.w, a3, b3);
            uint2 phv; phv.x = pack2(a0, a1); phv.y = pack2(a2, a3);
            uint2 plv; plv.x = pack2(b0, b1); plv.y = pack2(b2, b3);
            int byt = m * 256 + ((8 * j) ^ ((m & 7) << 4));
            *(uint2*)(AHI + byt) = phv;
            *(uint2*)(ALO + byt) = plv;
        }
        __syncthreads();

        // MMA: 5 m-tiles of 16 rows
        for (int m = 0; m < 5; m++) {
            float acc[16];
            int rb0 = (m * 16 + g) * 256;
            int rb1 = rb0 + 2048;
            if (is_rz) mma_m_tile<8, 2>(AHI, ALO, bh, bl, acc, rb0, rb1, aoff, swA, tg);
            else       mma_m_tile<4, 4>(AHI, ALO, bh, bl, acc, rb0, rb1, aoff, swA, tg);

            int row0 = m * 16 + g;
            int swG = g << 5;
            if (role == 0) {
#pragma unroll
                for (int nt = 0; nt < 2; nt++) {
                    int b = (4 * (wid * 16 + nt * 8 + tg * 2)) ^ swG;
                    *(float2*)(GRZ + row0 * 512 + b)       = make_float2(acc[nt * 4 + 0], acc[nt * 4 + 1]);
                    *(float2*)(GRZ + (row0 + 8) * 512 + b) = make_float2(acc[nt * 4 + 2], acc[nt * 4 + 3]);
                }
            } else {
                char* Gp = (role == 1) ? GX : GH;
                int wb = (role == 1) ? (wid - 8) : (wid - 10);
#pragma unroll
                for (int nt = 0; nt < 4; nt++) {
                    int b = (4 * (wb * 32 + nt * 8 + tg * 2)) ^ swG;
                    *(float2*)(Gp + row0 * 256 + b)       = make_float2(acc[nt * 4 + 0], acc[nt * 4 + 1]);
                    *(float2*)(Gp + (row0 + 8) * 256 + b) = make_float2(acc[nt * 4 + 2], acc[nt * 4 + 3]);
                }
            }
        }
        __syncthreads();

        // gates: 2560 i-pairs
        for (int p = tid; p < MB * 32; p += 384) {
            int row = p >> 5, jp = p & 31;
            int sw = (row & 7) << 5;
            int o = (8 * jp) ^ sw;
            float2 rv = *(float2*)(GRZ + row * 512 + o);
            float2 zv = *(float2*)(GRZ + row * 512 + 256 + o);
            float2 xv = *(float2*)(GX + row * 256 + o);
            float2 hv = *(float2*)(GH + row * 256 + o);
            int i0 = 2 * jp;
            float hp0 = hS[row * 64 + i0], hp1 = hS[row * 64 + i0 + 1];
            float r0 = sigmoid_fast(rv.x + bias[i0]);
            float r1 = sigmoid_fast(rv.y + bias[i0 + 1]);
            float z0 = sigmoid_fast(zv.x + bias[64 + i0]);
            float z1 = sigmoid_fast(zv.y + bias[64 + i0 + 1]);
            float n0 = tanh_fast(xv.x + bias[128 + i0]     + r0 * (hv.x + bias[192 + i0]));
            float n1 = tanh_fast(xv.y + bias[128 + i0 + 1] + r1 * (hv.y + bias[192 + i0 + 1]));
            float o0 = fmaf(z0, hp0 - n0, n0);
            float o1 = fmaf(z1, hp1 - n1, n1);
            hS[row * 64 + i0] = o0;
            hS[row * 64 + i0 + 1] = o1;
            __nv_bfloat16 e0, f0, e1, f1;
            split_bf16(o0, e0, f0);
            split_bf16(o1, e1, f1);
            int ba = row * 256 + 128 + ((4 * jp) ^ ((row & 7) << 4));
            *(u32*)(AHI + ba) = pack2(e0, e1);
            *(u32*)(ALO + ba) = pack2(f0, f1);
            *(float2*)(&outp[((size_t)(node0 + row) * TT + t) * 64 + i0]) = make_float2(o0, o1);
        }
        __syncthreads();
    }
}

// ---------------- attention + fc + residual --------------------------------
__global__ void k_attn(const float* __restrict__ attn_w, const float* __restrict__ attn_b,
                       const float* __restrict__ fc_w,   const float* __restrict__ fc_b,
                       const float* __restrict__ x, float* __restrict__ out) {
    int gt = blockIdx.x * blockDim.x + threadIdx.x;
    int node = gt >> 5, lane = gt & 31;
    if (node >= NN) return;
    const float* hb = &g_hb[(size_t)node * TT * HH];
    float aw0 = attn_w[lane], aw1 = attn_w[lane + 32];
    float s[TT];
#pragma unroll
    for (int t = 0; t < TT; t++) {
        float p = hb[t * HH + lane] * aw0 + hb[t * HH + lane + 32] * aw1;
#pragma unroll
        for (int o = 16; o > 0; o >>= 1) p += __shfl_xor_sync(0xffffffffu, p, o);
        s[t] = p + attn_b[0];
    }
    float mx = s[0];
#pragma unroll
    for (int t = 1; t < TT; t++) mx = fmaxf(mx, s[t]);
    float Z = 0.f;
#pragma unroll
    for (int t = 0; t < TT; t++) { s[t] = expf(s[t] - mx); Z += s[t]; }
    float inv = 1.0f / Z;
    float c0 = 0.f, c1 = 0.f;
#pragma unroll
    for (int t = 0; t < TT; t++) {
        float p = s[t] * inv;
        c0 = fmaf(p, hb[t * HH + lane], c0);
        c1 = fmaf(p, hb[t * HH + lane + 32], c1);
    }
    float res = c0 * fc_w[lane] + c1 * fc_w[lane + 32];
#pragma unroll
    for (int o = 16; o > 0; o >>= 1) res += __shfl_xor_sync(0xffffffffu, res, o);
    if (lane == 0) {
        float last = x[((TT - 1) * NN + node) * FIN + 0];
        out[node] = last + res + fc_b[0];
    }
}

// ---------------- launch ----------------------------------------------------
extern "C" void kernel_launch(void* const* d_in, const int* in_sizes, int n_in,
                              void* d_out, int out_size) {
    const float* x      = (const float*)d_in[0];
    const int*   ei     = (const int*)  d_in[1];
    const float* gcn_w  = (const float*)d_in[2];
    const float* gcn_b  = (const float*)d_in[3];
    const float* w_ih0  = (const float*)d_in[4];
    const float* w_hh0  = (const float*)d_in[5];
    const float* b_ih0  = (const float*)d_in[6];
    const float* b_hh0  = (const float*)d_in[7];
    const float* w_ih1  = (const float*)d_in[8];
    const float* w_hh1  = (const float*)d_in[9];
    const float* b_ih1  = (const float*)d_in[10];
    const float* b_hh1  = (const float*)d_in[11];
    const float* attn_w = (const float*)d_in[12];
    const float* attn_b = (const float*)d_in[13];
    const float* fc_w   = (const float*)d_in[14];
    const float* fc_b   = (const float*)d_in[15];
    float* out = (float*)d_out;

    cudaFuncSetAttribute(k_rec_mma, cudaFuncAttributeMaxDynamicSharedMemorySize, REC_SMEM);

    k_deg_init<<<(NN + 255) / 256, 256>>>();
    k_deg_edge<<<(NE + 255) / 256, 256>>>(ei);
    k_dis<<<(NN + 255) / 256, 256>>>();
    k_agg_init<<<(NN * TT * FIN + 255) / 256, 256>>>(x);
    k_edge_agg<<<(NE * 32 + 255) / 256, 256>>>(ei, x);
    k_gcn<<<NT / 4, 256>>>(gcn_w, gcn_b);

    k_rec_mma<<<GRID_REC, 384, REC_SMEM>>>(w_ih0, w_hh0, b_ih0, b_hh0, 0);
    k_rec_mma<<<GRID_REC, 384, REC_SMEM>>>(w_ih1, w_hh1, b_ih1, b_hh1, 1);

    k_attn<<<(NN * 32 + 255) / 256, 256>>>(attn_w, attn_b, fc_w, fc_b, x, out);
}

// round 6
// speedup vs baseline: 4.7303x; 1.1489x over previous
#include <cuda_runtime.h>
#include <cuda_bf16.h>
#include <math.h>

#define NN 10000      // nodes
#define TT 12         // seq len
#define FIN 16        // in channels
#define HH 64         // hidden
#define K3 192        // 3*H
#define NE 160000     // edges
#define NT (NN*TT)    // 120000 rows
#define MB 80         // nodes per block (10000 = 125 * 80)
#define GRID_REC 125

typedef unsigned int u32;
typedef unsigned long long u64;

// ---------------- scratch (device globals; no allocation allowed) ----------
__device__ float g_deg[NN];
__device__ float g_agg[NN * TT * FIN];
__device__ float g_ha [NN * TT * HH];

// ---------------- helpers ----------------------------------------------------
__device__ __forceinline__ float tanh_fast(float x) {
    float y; asm("tanh.approx.f32 %0, %1;" : "=f"(y) : "f"(x)); return y;
}
__device__ __forceinline__ float sigmoid_fast(float x) {
    return fmaf(0.5f, tanh_fast(0.5f * x), 0.5f);
}
__device__ __forceinline__ u32 pack2(__nv_bfloat16 a, __nv_bfloat16 b) {
    return (u32)__bfloat16_as_ushort(a) | ((u32)__bfloat16_as_ushort(b) << 16);
}
__device__ __forceinline__ void split_bf16(float v, __nv_bfloat16& hi, __nv_bfloat16& lo) {
    hi = __float2bfloat16(v);
    lo = __float2bfloat16(v - __bfloat162float(hi));
}
__device__ __forceinline__ void mma16816(float* c, const u32* a, u32 b0, u32 b1) {
    asm volatile(
        "mma.sync.aligned.m16n8k16.row.col.f32.bf16.bf16.f32 "
        "{%0,%1,%2,%3}, {%4,%5,%6,%7}, {%8,%9}, {%0,%1,%2,%3};"
        : "+f"(c[0]), "+f"(c[1]), "+f"(c[2]), "+f"(c[3])
        : "r"(a[0]), "r"(a[1]), "r"(a[2]), "r"(a[3]), "r"(b0), "r"(b1));
}

// ---------------- degree --------------------------------------------------
__global__ void k_deg_init() {
    int i = blockIdx.x * blockDim.x + threadIdx.x;
    if (i < NN) g_deg[i] = 1.0f;
}
__global__ void k_deg_edge(const int* __restrict__ ei) {
    int e = blockIdx.x * blockDim.x + threadIdx.x;
    if (e < NE) atomicAdd(&g_deg[ei[NE + e]], 1.0f);
}
// agg init (float4): agg[n,t,:] = x[t,n,:] * dis[n]^2
__global__ void k_agg_init(const float* __restrict__ x) {
    int idx = blockIdx.x * blockDim.x + threadIdx.x;
    if (idx >= NN * TT * 4) return;
    int n = idx / (TT * 4);
    int r = idx - n * (TT * 4);
    int t = r >> 2, f4 = r & 3;
    float di = rsqrtf(g_deg[n]);
    float c = di * di;
    float4 v = reinterpret_cast<const float4*>(x)[((size_t)t * NN + n) * 4 + f4];
    v.x *= c; v.y *= c; v.z *= c; v.w *= c;
    reinterpret_cast<float4*>(g_agg)[idx] = v;
}
__global__ void k_edge_agg(const int* __restrict__ ei, const float* __restrict__ x) {
    int gt = blockIdx.x * blockDim.x + threadIdx.x;
    int e = gt >> 5, lane = gt & 31;
    if (e >= NE) return;
    int s = ei[e];
    int d = ei[NE + e];
    float c = rsqrtf(g_deg[s]) * rsqrtf(g_deg[d]);
    const float4* x4 = reinterpret_cast<const float4*>(x);
    float4* dst4 = reinterpret_cast<float4*>(&g_agg[(size_t)d * (TT * FIN)]);
#pragma unroll
    for (int g = lane; g < 48; g += 32) {
        int t = g >> 2, f4 = g & 3;
        float4 v = x4[((size_t)t * NN + s) * 4 + f4];
        asm volatile("red.global.add.v4.f32 [%0], {%1, %2, %3, %4};"
                     :: "l"(dst4 + g), "f"(v.x * c), "f"(v.y * c), "f"(v.z * c), "f"(v.w * c)
                     : "memory");
    }
}

// ---------------- fused HMMA GRU layers --------------------------------------
// Layer 0: staging computes GCN (relu(agg@W+b)) inline from g_agg; writes g_ha.
// Layer 1: reads g_ha; gates phase feeds an online-softmax attention
//          accumulator; epilogue emits fc + residual directly to output.
// MMA core (unchanged from R5): 12 warps, m16n8k16 bf16, 3-term hi/lo split.
#define OFF_AHI 0
#define OFF_ALO 20480
#define OFF_GRZ 40960      // fp32 [80][128], swizzled
#define OFF_GX  81920      // fp32 [80][64]
#define OFF_GH  102400
#define OFF_HS  122880     // fp32 h state [80][64]
#define OFF_B   143360     // biases: 256 floats
#define OFF_EXT 144384     // L0: gcnW 4096 + gcnB 256 | L1: ctx 20480 + mZ 640 + aw 256 + fw 256
#define SMEM_L0 (OFF_EXT + 4096 + 256)
#define SMEM_L1 (OFF_EXT + 20480 + 640 + 256 + 256 + 16)

template<int KKS, int NTS>
__device__ __forceinline__ void mma_m_tile(
    const char* AHI, const char* ALO, const u32* bh, const u32* bl,
    float* acc, int rb0, int rb1, int aoff, int swA, int tg)
{
#pragma unroll
    for (int q = 0; q < NTS * 4; q++) acc[q] = 0.0f;
#pragma unroll
    for (int kk = 0; kk < KKS; kk++) {
        int c0 = aoff + ((kk * 32 + 4 * tg) ^ swA);
        int c2 = aoff + ((kk * 32 + 16 + 4 * tg) ^ swA);
        u32 ah[4], al[4];
        ah[0] = *(const u32*)(AHI + rb0 + c0); ah[1] = *(const u32*)(AHI + rb1 + c0);
        ah[2] = *(const u32*)(AHI + rb0 + c2); ah[3] = *(const u32*)(AHI + rb1 + c2);
        al[0] = *(const u32*)(ALO + rb0 + c0); al[1] = *(const u32*)(ALO + rb1 + c0);
        al[2] = *(const u32*)(ALO + rb0 + c2); al[3] = *(const u32*)(ALO + rb1 + c2);
#pragma unroll
        for (int nt = 0; nt < NTS; nt++) {
            int f = kk * NTS + nt;
            mma16816(acc + nt * 4, ah, bh[2 * f], bh[2 * f + 1]);
            mma16816(acc + nt * 4, ah, bl[2 * f], bl[2 * f + 1]);
            mma16816(acc + nt * 4, al, bh[2 * f], bh[2 * f + 1]);
        }
    }
}

template<int L>
__global__ __launch_bounds__(384, 1) void k_rec(
    const float* __restrict__ wih, const float* __restrict__ whh,
    const float* __restrict__ bih, const float* __restrict__ bhh,
    const float* __restrict__ gwp, const float* __restrict__ gbp,
    const float* __restrict__ awp, const float* __restrict__ abp,
    const float* __restrict__ fwp, const float* __restrict__ fbp,
    const float* __restrict__ x,   float* __restrict__ outv)
{
    extern __shared__ __align__(16) char sm[];
    char* AHI = sm + OFF_AHI;
    char* ALO = sm + OFF_ALO;
    char* GRZ = sm + OFF_GRZ;
    char* GX  = sm + OFF_GX;
    char* GH  = sm + OFF_GH;
    float* hS   = (float*)(sm + OFF_HS);
    float* bias = (float*)(sm + OFF_B);
    // layer-specific smem
    float* gwS = (float*)(sm + OFF_EXT);               // L0: [16][64]
    float* gbS = (float*)(sm + OFF_EXT + 4096);        // L0: [64]
    float* ctx = (float*)(sm + OFF_EXT);               // L1: [80][64]
    float* mS  = (float*)(sm + OFF_EXT + 20480);       // L1: [80]
    float* ZS  = (float*)(sm + OFF_EXT + 20480 + 320); // L1: [80]
    float* awS = (float*)(sm + OFF_EXT + 21120);       // L1: [64]
    float* fwS = (float*)(sm + OFF_EXT + 21376);       // L1: [64]
    float* scS = (float*)(sm + OFF_EXT + 21632);       // L1: [ab]

    int tid = threadIdx.x, wid = tid >> 5, lid = tid & 31;
    int g = lid >> 2, tg = lid & 3;
    int node0 = blockIdx.x * MB;

    // biases: [0..127]=bih+bhh (r|z), [128..191]=bih_n, [192..255]=bhh_n
    if (tid < 128) bias[tid] = bih[tid] + bhh[tid];
    else if (tid < 192) bias[tid] = bih[tid];
    else if (tid < 256) bias[tid] = bhh[tid - 64];

    if (L == 0) {
        for (int i = tid; i < FIN * HH; i += 384) gwS[i] = gwp[i];
        if (tid < 64) gbS[tid] = gbp[tid];
    } else {
        for (int i = tid; i < MB * 64; i += 384) ctx[i] = 0.0f;
        if (tid < MB) { mS[tid] = -3.0e38f; ZS[tid] = 0.0f; }
        if (tid < 64) { awS[tid] = awp[tid]; fwS[tid] = fwp[tid]; }
        if (tid == 0) scS[0] = abp[0];
    }

    // zero A tiles (H half => h0 = 0) and fp32 h state
    {
        uint4 z = make_uint4(0, 0, 0, 0);
        for (int i = tid; i < 2560; i += 384) {
            ((uint4*)AHI)[i] = z;
            ((uint4*)ALO)[i] = z;
        }
        for (int i = tid; i < MB * 64; i += 384) hS[i] = 0.0f;
    }

    bool is_rz = wid < 8;
    int role = is_rz ? 0 : (wid < 10 ? 1 : 2);

    // persistent B fragments (hi/lo)
    u32 bh[32], bl[32];
#pragma unroll
    for (int f = 0; f < 16; f++) {
        int kk = is_rz ? (f >> 1) : (f >> 2);
        int nt = is_rz ? (f & 1)  : (f & 3);
        int nrow;
        if (role == 0)      nrow = wid * 16 + nt * 8 + g;
        else if (role == 1) nrow = 128 + (wid - 8) * 32 + nt * 8 + g;
        else                nrow = 128 + (wid - 10) * 32 + nt * 8 + g;
#pragma unroll
        for (int r = 0; r < 2; r++) {
            int k = kk * 16 + tg * 2 + r * 8;
            float w0, w1;
            if (role == 0) {
                if (k < 64) { w0 = wih[nrow * 64 + k];      w1 = wih[nrow * 64 + k + 1]; }
                else        { w0 = whh[nrow * 64 + k - 64]; w1 = whh[nrow * 64 + k - 63]; }
            } else if (role == 1) {
                w0 = wih[nrow * 64 + k]; w1 = wih[nrow * 64 + k + 1];
            } else {
                w0 = whh[nrow * 64 + k]; w1 = whh[nrow * 64 + k + 1];
            }
            __nv_bfloat16 h0, l0, h1, l1;
            split_bf16(w0, h0, l0);
            split_bf16(w1, h1, l1);
            bh[2 * f + r] = pack2(h0, h1);
            bl[2 * f + r] = pack2(l0, l1);
        }
    }

    int aoff = (role == 2) ? 128 : 0;
    int swA = g << 4;
    const float4* in4 = reinterpret_cast<const float4*>(g_ha);
    float aw0 = 0.f, aw1 = 0.f, ab = 0.f;
    __syncthreads();
    if (L == 1) { aw0 = awS[2 * lid]; aw1 = awS[2 * lid + 1]; ab = scS[0]; }

    for (int t = 0; t < TT; t++) {
        // ---- stage X(t) into A tile (bf16 hi/lo, swizzled) ----
        if (L == 0) {
            // inline GCN: X = relu(agg@W + b), agg row = 16 ch
            for (int i = tid; i < MB * 16; i += 384) {
                int m = i >> 4, j = i & 15;   // j = float4 col group
                const float4* ar = reinterpret_cast<const float4*>(
                    &g_agg[(((size_t)(node0 + m)) * TT + t) * 16]);
                float4 a0 = ar[0], a1 = ar[1], a2 = ar[2], a3 = ar[3];
                float s0 = gbS[4 * j], s1 = gbS[4 * j + 1], s2 = gbS[4 * j + 2], s3 = gbS[4 * j + 3];
                const float* af = (const float*)&a0;
#pragma unroll
                for (int f = 0; f < 16; f++) {
                    float av;
                    if (f < 4) av = ((const float*)&a0)[f];
                    else if (f < 8) av = ((const float*)&a1)[f - 4];
                    else if (f < 12) av = ((const float*)&a2)[f - 8];
                    else av = ((const float*)&a3)[f - 12];
                    const float4 wv = reinterpret_cast<const float4*>(gwS)[f * 16 + j];
                    s0 = fmaf(av, wv.x, s0);
                    s1 = fmaf(av, wv.y, s1);
                    s2 = fmaf(av, wv.z, s2);
                    s3 = fmaf(av, wv.w, s3);
                }
                (void)af;
                s0 = fmaxf(s0, 0.f); s1 = fmaxf(s1, 0.f);
                s2 = fmaxf(s2, 0.f); s3 = fmaxf(s3, 0.f);
                __nv_bfloat16 e0, f0, e1, f1, e2, f2, e3, f3;
                split_bf16(s0, e0, f0); split_bf16(s1, e1, f1);
                split_bf16(s2, e2, f2); split_bf16(s3, e3, f3);
                uint2 phv; phv.x = pack2(e0, e1); phv.y = pack2(e2, e3);
                uint2 plv; plv.x = pack2(f0, f1); plv.y = pack2(f2, f3);
                int byt = m * 256 + ((8 * j) ^ ((m & 7) << 4));
                *(uint2*)(AHI + byt) = phv;
                *(uint2*)(ALO + byt) = plv;
            }
        } else {
            for (int i = tid; i < MB * 16; i += 384) {
                int m = i >> 4, j = i & 15;
                float4 v = in4[((size_t)(node0 + m) * TT + t) * 16 + j];
                __nv_bfloat16 a0, b0, a1, b1, a2, b2, a3, b3;
                split_bf16(v.x, a0, b0); split_bf16(v.y, a1, b1);
                split_bf16(v.z, a2, b2); split_bf16(v.w, a3, b3);
                uint2 phv; phv.x = pack2(a0, a1); phv.y = pack2(a2, a3);
                uint2 plv; plv.x = pack2(b0, b1); plv.y = pack2(b2, b3);
                int byt = m * 256 + ((8 * j) ^ ((m & 7) << 4));
                *(uint2*)(AHI + byt) = phv;
                *(uint2*)(ALO + byt) = plv;
            }
        }
        __syncthreads();

        // ---- MMA: 5 m-tiles of 16 rows ----
        for (int m = 0; m < 5; m++) {
            float acc[16];
            int rb0 = (m * 16 + g) * 256;
            int rb1 = rb0 + 2048;
            if (is_rz) mma_m_tile<8, 2>(AHI, ALO, bh, bl, acc, rb0, rb1, aoff, swA, tg);
            else       mma_m_tile<4, 4>(AHI, ALO, bh, bl, acc, rb0, rb1, aoff, swA, tg);

            int row0 = m * 16 + g;
            int swG = g << 5;
            if (role == 0) {
#pragma unroll
                for (int nt = 0; nt < 2; nt++) {
                    int b = (4 * (wid * 16 + nt * 8 + tg * 2)) ^ swG;
                    *(float2*)(GRZ + row0 * 512 + b)       = make_float2(acc[nt * 4 + 0], acc[nt * 4 + 1]);
                    *(float2*)(GRZ + (row0 + 8) * 512 + b) = make_float2(acc[nt * 4 + 2], acc[nt * 4 + 3]);
                }
            } else {
                char* Gp = (role == 1) ? GX : GH;
                int wb = (role == 1) ? (wid - 8) : (wid - 10);
#pragma unroll
                for (int nt = 0; nt < 4; nt++) {
                    int b = (4 * (wb * 32 + nt * 8 + tg * 2)) ^ swG;
                    *(float2*)(Gp + row0 * 256 + b)       = make_float2(acc[nt * 4 + 0], acc[nt * 4 + 1]);
                    *(float2*)(Gp + (row0 + 8) * 256 + b) = make_float2(acc[nt * 4 + 2], acc[nt * 4 + 3]);
                }
            }
        }
        __syncthreads();

        // ---- gates (+ L1: online-softmax attention) ----
        for (int p = tid; p < MB * 32; p += 384) {
            int row = p >> 5, jp = p & 31;       // row is warp-uniform
            int sw = (row & 7) << 5;
            int o = (8 * jp) ^ sw;
            float2 rv = *(float2*)(GRZ + row * 512 + o);
            float2 zv = *(float2*)(GRZ + row * 512 + 256 + o);
            float2 xv = *(float2*)(GX + row * 256 + o);
            float2 hv = *(float2*)(GH + row * 256 + o);
            int i0 = 2 * jp;
            float hp0 = hS[row * 64 + i0], hp1 = hS[row * 64 + i0 + 1];
            float r0 = sigmoid_fast(rv.x + bias[i0]);
            float r1 = sigmoid_fast(rv.y + bias[i0 + 1]);
            float z0 = sigmoid_fast(zv.x + bias[64 + i0]);
            float z1 = sigmoid_fast(zv.y + bias[64 + i0 + 1]);
            float n0 = tanh_fast(xv.x + bias[128 + i0]     + r0 * (hv.x + bias[192 + i0]));
            float n1 = tanh_fast(xv.y + bias[128 + i0 + 1] + r1 * (hv.y + bias[192 + i0 + 1]));
            float o0 = fmaf(z0, hp0 - n0, n0);
            float o1 = fmaf(z1, hp1 - n1, n1);
            hS[row * 64 + i0] = o0;
            hS[row * 64 + i0 + 1] = o1;
            __nv_bfloat16 e0, f0, e1, f1;
            split_bf16(o0, e0, f0);
            split_bf16(o1, e1, f1);
            int ba = row * 256 + 128 + ((4 * jp) ^ ((row & 7) << 4));
            *(u32*)(AHI + ba) = pack2(e0, e1);
            *(u32*)(ALO + ba) = pack2(f0, f1);
            if (L == 0) {
                *(float2*)(&g_ha[((size_t)(node0 + row) * TT + t) * 64 + i0]) = make_float2(o0, o1);
            } else {
                // online softmax attention over t
                float sc = o0 * aw0 + o1 * aw1;
#pragma unroll
                for (int of = 16; of > 0; of >>= 1) sc += __shfl_xor_sync(0xffffffffu, sc, of);
                sc += ab;
                float m_old = mS[row];
                float mn = fmaxf(m_old, sc);
                float ea = __expf(m_old - mn);
                float eb = __expf(sc - mn);
                ctx[row * 64 + i0]     = ctx[row * 64 + i0]     * ea + eb * o0;
                ctx[row * 64 + i0 + 1] = ctx[row * 64 + i0 + 1] * ea + eb * o1;
                if (jp == 0) { mS[row] = mn; ZS[row] = ZS[row] * ea + eb; }
            }
        }
        __syncthreads();
    }

    // ---- L1 epilogue: fc + residual -> output ----
    if (L == 1) {
        float fw0 = fwS[2 * lid], fw1 = fwS[2 * lid + 1];
        for (int row = wid; row < MB; row += 12) {
            float v = ctx[row * 64 + 2 * lid] * fw0 + ctx[row * 64 + 2 * lid + 1] * fw1;
#pragma unroll
            for (int of = 16; of > 0; of >>= 1) v += __shfl_xor_sync(0xffffffffu, v, of);
            if (lid == 0) {
                int node = node0 + row;
                float last = x[((size_t)(TT - 1) * NN + node) * FIN];
                outv[node] = last + v / ZS[row] + fbp[0];
            }
        }
    }
}

// ---------------- launch ----------------------------------------------------
extern "C" void kernel_launch(void* const* d_in, const int* in_sizes, int n_in,
                              void* d_out, int out_size) {
    const float* x      = (const float*)d_in[0];
    const int*   ei     = (const int*)  d_in[1];
    const float* gcn_w  = (const float*)d_in[2];
    const float* gcn_b  = (const float*)d_in[3];
    const float* w_ih0  = (const float*)d_in[4];
    const float* w_hh0  = (const float*)d_in[5];
    const float* b_ih0  = (const float*)d_in[6];
    const float* b_hh0  = (const float*)d_in[7];
    const float* w_ih1  = (const float*)d_in[8];
    const float* w_hh1  = (const float*)d_in[9];
    const float* b_ih1  = (const float*)d_in[10];
    const float* b_hh1  = (const float*)d_in[11];
    const float* attn_w = (const float*)d_in[12];
    const float* attn_b = (const float*)d_in[13];
    const float* fc_w   = (const float*)d_in[14];
    const float* fc_b   = (const float*)d_in[15];
    float* out = (float*)d_out;

    cudaFuncSetAttribute(k_rec<0>, cudaFuncAttributeMaxDynamicSharedMemorySize, SMEM_L0);
    cudaFuncSetAttribute(k_rec<1>, cudaFuncAttributeMaxDynamicSharedMemorySize, SMEM_L1);

    k_deg_init<<<(NN + 255) / 256, 256>>>();
    k_deg_edge<<<(NE + 255) / 256, 256>>>(ei);
    k_agg_init<<<(NN * TT * 4 + 255) / 256, 256>>>(x);
    k_edge_agg<<<(NE * 32 + 255) / 256, 256>>>(ei, x);

    k_rec<0><<<GRID_REC, 384, SMEM_L0>>>(w_ih0, w_hh0, b_ih0, b_hh0,
                                         gcn_w, gcn_b, nullptr, nullptr, nullptr, nullptr,
                                         x, nullptr);
    k_rec<1><<<GRID_REC, 384, SMEM_L1>>>(w_ih1, w_hh1, b_ih1, b_hh1,
                                         nullptr, nullptr, attn_w, attn_b, fc_w, fc_b,
                                         x, out);
}